// round 1
// baseline (speedup 1.0000x reference)
#include <cuda_runtime.h>

#define NE 768
#define HEAD 64
#define TT 2048
#define BB 8
#define PS 68   // padded smem row stride (floats), conflict-free for row-indexed loads

__device__ float g_q[BB * TT * HEAD];   // 4MB scratch for projected q (=k=v)

// ---------------------------------------------------------------------------
// Projection: q[b,t,h] = sum_c x[b,t,c] * Wq[c,h]
// Tile: 128 rows x 64 cols per block, K-chunks of 32. 256 threads, 8x4 micro.
// ---------------------------------------------------------------------------
__global__ __launch_bounds__(256) void proj_kernel(const float* __restrict__ x,
                                                   const float* __restrict__ Wq) {
    __shared__ float xs[128 * 33];
    __shared__ float ws[32 * 64];
    int b = blockIdx.y;
    int t0 = blockIdx.x * 128;
    int tid = threadIdx.x;
    const float* xb = x + ((size_t)b * TT + t0) * NE;

    float acc[8][4];
#pragma unroll
    for (int i = 0; i < 8; i++)
#pragma unroll
        for (int j = 0; j < 4; j++) acc[i][j] = 0.f;

    int tr = tid >> 4, tc = tid & 15;
    int r0 = tr * 8, c0 = tc * 4;

    for (int kc = 0; kc < NE; kc += 32) {
        __syncthreads();
#pragma unroll
        for (int i = 0; i < 16; i++) {
            int e = tid + i * 256;
            int r = e >> 5, c = e & 31;
            xs[r * 33 + c] = xb[r * NE + kc + c];
        }
#pragma unroll
        for (int i = 0; i < 8; i++) {
            int e = tid + i * 256;
            int kk = e >> 6, h = e & 63;
            ws[kk * 64 + h] = Wq[(kc + kk) * HEAD + h];
        }
        __syncthreads();
#pragma unroll
        for (int kk = 0; kk < 32; kk++) {
            float4 b4 = *(const float4*)(ws + kk * 64 + c0);
#pragma unroll
            for (int ri = 0; ri < 8; ri++) {
                float a = xs[(r0 + ri) * 33 + kk];
                acc[ri][0] += a * b4.x;
                acc[ri][1] += a * b4.y;
                acc[ri][2] += a * b4.z;
                acc[ri][3] += a * b4.w;
            }
        }
    }
    float* qb = g_q + ((size_t)b * TT + t0) * HEAD;
#pragma unroll
    for (int ri = 0; ri < 8; ri++) {
        float4 v = make_float4(acc[ri][0], acc[ri][1], acc[ri][2], acc[ri][3]);
        *(float4*)(qb + (r0 + ri) * HEAD + c0) = v;
    }
}

// ---------------------------------------------------------------------------
// Flash attention: q=k=v, causal, bias(t,s)=rel[s-t+2047], scale 1/8.
// Block = 64 query rows (one batch), 8 warps x 8 rows. Key tiles of 64.
// Each lane owns score columns {l, l+32} and output dims {l, l+32}.
// ---------------------------------------------------------------------------
__global__ __launch_bounds__(256) void attn_kernel(const float* __restrict__ rel,
                                                   float* __restrict__ out) {
    extern __shared__ float sm[];
    float* Qs = sm;                 // 64 * PS
    float* Ks = Qs + 64 * PS;       // 64 * PS  (also V)
    float* Pall = Ks + 64 * PS;     // 8 warps * 8 * PS
    float* Wb = Pall + 64 * PS;     // 128-float bias window

    int b = blockIdx.y;
    int i_tile = (int)gridDim.x - 1 - (int)blockIdx.x;   // heavy tiles first
    int t0 = i_tile * 64;
    int tid = threadIdx.x;
    int w = tid >> 5, l = tid & 31;
    const float* qb = g_q + (size_t)b * TT * HEAD;

    // Load Q tile
#pragma unroll
    for (int i = 0; i < 16; i++) {
        int e = tid + i * 256;
        int r = e >> 6, c = e & 63;
        Qs[r * PS + c] = qb[(t0 + r) * HEAD + c];
    }

    float m[8], lsum[8], o0[8], o1[8];
#pragma unroll
    for (int r = 0; r < 8; r++) { m[r] = -1e30f; lsum[r] = 0.f; o0[r] = 0.f; o1[r] = 0.f; }

    float* Pw = Pall + w * 8 * PS;
    int rr0 = w * 8;

    for (int j = 0; j <= i_tile; j++) {
        __syncthreads();                       // prev-iter Ks reads complete
        const float* kb = qb + j * 64 * HEAD;
#pragma unroll
        for (int i = 0; i < 16; i++) {
            int e = tid + i * 256;
            int r = e >> 6, c = e & 63;
            Ks[r * PS + c] = kb[r * HEAD + c];
        }
        // bias window: Wb[d] = rel[64*(j-i) + d - 63 + 2047], d in [0,127)
        if (tid < 127) Wb[tid] = rel[64 * (j - i_tile) + tid + 1984];
        __syncthreads();

        // ---- S = Q K^T (lane: 8 rows x cols {l, l+32}) ----
        float acc0[8], acc1[8];
#pragma unroll
        for (int r = 0; r < 8; r++) { acc0[r] = 0.f; acc1[r] = 0.f; }
        const float4* k4a = (const float4*)(Ks + l * PS);
        const float4* k4b = (const float4*)(Ks + (l + 32) * PS);
#pragma unroll
        for (int h4 = 0; h4 < 16; h4++) {
            float4 k0 = k4a[h4];
            float4 k1 = k4b[h4];
#pragma unroll
            for (int r = 0; r < 8; r++) {
                float4 q = ((const float4*)(Qs + (rr0 + r) * PS))[h4];
                acc0[r] += q.x * k0.x + q.y * k0.y + q.z * k0.z + q.w * k0.w;
                acc1[r] += q.x * k1.x + q.y * k1.y + q.z * k1.z + q.w * k1.w;
            }
        }

        bool diag = (j == i_tile);
        // ---- scale + bias + mask + online softmax ----
#pragma unroll
        for (int r = 0; r < 8; r++) {
            int rr = rr0 + r;
            float s0 = acc0[r] * 0.125f + Wb[l - rr + 63];
            float s1 = acc1[r] * 0.125f + Wb[l - rr + 95];
            if (diag) {
                if (l > rr) s0 = -1e30f;
                if (l + 32 > rr) s1 = -1e30f;
            }
            float mx = fmaxf(s0, s1);
#pragma unroll
            for (int off = 16; off; off >>= 1)
                mx = fmaxf(mx, __shfl_xor_sync(0xffffffffu, mx, off));
            float mnew = fmaxf(m[r], mx);
            float p0 = __expf(s0 - mnew);
            float p1 = __expf(s1 - mnew);
            float ps = p0 + p1;
#pragma unroll
            for (int off = 16; off; off >>= 1)
                ps += __shfl_xor_sync(0xffffffffu, ps, off);
            float alpha = __expf(m[r] - mnew);
            lsum[r] = lsum[r] * alpha + ps;
            m[r] = mnew;
            o0[r] *= alpha;
            o1[r] *= alpha;
            Pw[r * PS + l] = p0;
            Pw[r * PS + l + 32] = p1;
        }
        __syncwarp();

        // ---- O += P * V (V = Ks). Lane owns output dims {l, l+32}. ----
#pragma unroll
        for (int cb = 0; cb < 64; cb += 8) {
            float v0[8], v1[8];
#pragma unroll
            for (int cc = 0; cc < 8; cc++) {
                v0[cc] = Ks[(cb + cc) * PS + l];
                v1[cc] = Ks[(cb + cc) * PS + l + 32];
            }
#pragma unroll
            for (int r = 0; r < 8; r++) {
                float4 pa = *(const float4*)(Pw + r * PS + cb);
                float4 pb = *(const float4*)(Pw + r * PS + cb + 4);
                o0[r] += pa.x * v0[0] + pa.y * v0[1] + pa.z * v0[2] + pa.w * v0[3]
                       + pb.x * v0[4] + pb.y * v0[5] + pb.z * v0[6] + pb.w * v0[7];
                o1[r] += pa.x * v1[0] + pa.y * v1[1] + pa.z * v1[2] + pa.w * v1[3]
                       + pb.x * v1[4] + pb.y * v1[5] + pb.z * v1[6] + pb.w * v1[7];
            }
        }
        // Pw reuse next iter is after __syncthreads + S-compute: safe in-warp.
    }

    float* ob = out + (size_t)b * TT * HEAD;
#pragma unroll
    for (int r = 0; r < 8; r++) {
        float inv = 1.0f / lsum[r];
        int t = t0 + rr0 + r;
        ob[t * HEAD + l] = o0[r] * inv;
        ob[t * HEAD + l + 32] = o1[r] * inv;
    }
}

// ---------------------------------------------------------------------------
extern "C" void kernel_launch(void* const* d_in, const int* in_sizes, int n_in,
                              void* d_out, int out_size) {
    const float* x   = (const float*)d_in[0];
    const float* Wq  = (const float*)d_in[1];
    const float* rel = (const float*)d_in[2];
    float* out = (float*)d_out;

    const int smem_bytes = (64 * PS * 3 + 128) * (int)sizeof(float);  // 52736 B
    cudaFuncSetAttribute(attn_kernel, cudaFuncAttributeMaxDynamicSharedMemorySize,
                         smem_bytes);

    dim3 pgrid(TT / 128, BB);
    proj_kernel<<<pgrid, 256>>>(x, Wq);

    dim3 agrid(TT / 64, BB);
    attn_kernel<<<agrid, 256, smem_bytes>>>(rel, out);
}

// round 4
// speedup vs baseline: 1.4317x; 1.4317x over previous
#include <cuda_runtime.h>

#define NE 768
#define HEAD 64
#define TT 2048
#define BB 8
#define PS 68   // padded smem row stride (floats)

__device__ float g_q[BB * TT * HEAD];   // 4MB scratch for projected q (=k=v)

// ---------------------------------------------------------------------------
// Projection: q[b,t,h] = sum_c x[b,t,c] * Wq[c,h]
// 32-row x 64-col tiles, 128 threads, 4x4 micro-tile. Grid = 64 x 8 = 512 CTAs.
// ---------------------------------------------------------------------------
__global__ __launch_bounds__(128) void proj_kernel(const float* __restrict__ x,
                                                   const float* __restrict__ Wq) {
    __shared__ float xs[32 * 33];
    __shared__ float ws[32 * 64];
    int b = blockIdx.y;
    int t0 = blockIdx.x * 32;
    int tid = threadIdx.x;
    const float* xb = x + ((size_t)b * TT + t0) * NE;

    float acc[4][4];
#pragma unroll
    for (int i = 0; i < 4; i++)
#pragma unroll
        for (int j = 0; j < 4; j++) acc[i][j] = 0.f;

    int tr = tid >> 4, tc = tid & 15;     // 8 x 16 thread grid
    int r0 = tr * 4, c0 = tc * 4;

    for (int kc = 0; kc < NE; kc += 32) {
        __syncthreads();
#pragma unroll
        for (int i = 0; i < 8; i++) {     // xs: 32x32 = 1024 floats
            int e = tid + i * 128;
            int r = e >> 5, c = e & 31;
            xs[r * 33 + c] = xb[r * NE + kc + c];
        }
#pragma unroll
        for (int i = 0; i < 16; i++) {    // ws: 32x64 = 2048 floats
            int e = tid + i * 128;
            int kk = e >> 6, h = e & 63;
            ws[kk * 64 + h] = Wq[(kc + kk) * HEAD + h];
        }
        __syncthreads();
#pragma unroll
        for (int kk = 0; kk < 32; kk++) {
            float4 b4 = *(const float4*)(ws + kk * 64 + c0);
#pragma unroll
            for (int ri = 0; ri < 4; ri++) {
                float a = xs[(r0 + ri) * 33 + kk];
                acc[ri][0] += a * b4.x;
                acc[ri][1] += a * b4.y;
                acc[ri][2] += a * b4.z;
                acc[ri][3] += a * b4.w;
            }
        }
    }
    float* qb = g_q + ((size_t)b * TT + t0) * HEAD;
#pragma unroll
    for (int ri = 0; ri < 4; ri++) {
        *(float4*)(qb + (r0 + ri) * HEAD + c0) =
            make_float4(acc[ri][0], acc[ri][1], acc[ri][2], acc[ri][3]);
    }
}

// ---------------------------------------------------------------------------
// Flash attention: q=k=v, causal, bias(t,s)=rel[s-t+2047], scale 1/8.
// CTA = 128 threads (4 warps), Q-tile = 16 rows (4 rows/warp), K-tile = 64.
// Lane owns score/output columns {l, l+32}. Grid = 128 x 8 = 1024 CTAs.
// ---------------------------------------------------------------------------
__global__ __launch_bounds__(128, 6) void attn_kernel(const float* __restrict__ rel,
                                                      float* __restrict__ out) {
    __shared__ float Qs[16 * PS];
    __shared__ float Ks[64 * PS];
    __shared__ float Pall[16 * PS];
    __shared__ float Wb[80];

    int b = blockIdx.y;
    int i_tile = (int)gridDim.x - 1 - (int)blockIdx.x;   // heavy tiles first
    int t0 = i_tile * 16;
    int tid = threadIdx.x;
    int w = tid >> 5, l = tid & 31;
    const float* qb = g_q + (size_t)b * TT * HEAD;

    // Load Q tile: 16 rows x 16 float4 = 256 float4, 2 per thread
#pragma unroll
    for (int i = 0; i < 2; i++) {
        int e = tid + i * 128;
        int r = e >> 4, c4 = e & 15;
        *(float4*)(Qs + r * PS + c4 * 4) =
            *(const float4*)(qb + (t0 + r) * HEAD + c4 * 4);
    }

    float m[4], lsum[4], o0[4], o1[4];
#pragma unroll
    for (int r = 0; r < 4; r++) { m[r] = -1e30f; lsum[r] = 0.f; o0[r] = 0.f; o1[r] = 0.f; }

    float* Pw = Pall + w * 4 * PS;
    int rr0 = w * 4;
    int jmax = (t0 + 15) >> 6;

    for (int j = 0; j <= jmax; j++) {
        __syncthreads();                      // prev-iter Ks reads complete
        const float* kb = qb + (size_t)j * 64 * HEAD;
#pragma unroll
        for (int i = 0; i < 8; i++) {         // K tile: 64 x 16 float4
            int e = tid + i * 128;
            int r = e >> 4, c4 = e & 15;
            *(float4*)(Ks + r * PS + c4 * 4) =
                *(const float4*)(kb + r * HEAD + c4 * 4);
        }
        // bias window: idx = s - t + 2047 = (64j - t0 + 2032) + (c - rr + 15)
        if (tid < 80) Wb[tid] = rel[64 * j - t0 + 2032 + tid];
        __syncthreads();

        // ---- S = Q K^T (lane: 4 rows x cols {l, l+32}) ----
        float acc0[4], acc1[4];
#pragma unroll
        for (int r = 0; r < 4; r++) { acc0[r] = 0.f; acc1[r] = 0.f; }
        const float4* k4a = (const float4*)(Ks + l * PS);
        const float4* k4b = (const float4*)(Ks + (l + 32) * PS);
#pragma unroll
        for (int h4 = 0; h4 < 16; h4++) {
            float4 k0 = k4a[h4];
            float4 k1 = k4b[h4];
#pragma unroll
            for (int r = 0; r < 4; r++) {
                float4 q = ((const float4*)(Qs + (rr0 + r) * PS))[h4];
                acc0[r] += q.x * k0.x + q.y * k0.y + q.z * k0.z + q.w * k0.w;
                acc1[r] += q.x * k1.x + q.y * k1.y + q.z * k1.z + q.w * k1.w;
            }
        }

        bool diag = (j == jmax);
        // ---- scale + bias + mask + online softmax ----
#pragma unroll
        for (int r = 0; r < 4; r++) {
            int rr = rr0 + r;
            float s0 = acc0[r] * 0.125f + Wb[l - rr + 15];
            float s1 = acc1[r] * 0.125f + Wb[l - rr + 47];
            if (diag) {
                int t = t0 + rr;
                if (64 * j + l > t) s0 = -1e30f;
                if (64 * j + l + 32 > t) s1 = -1e30f;
            }
            float mx = fmaxf(s0, s1);
#pragma unroll
            for (int off = 16; off; off >>= 1)
                mx = fmaxf(mx, __shfl_xor_sync(0xffffffffu, mx, off));
            float mnew = fmaxf(m[r], mx);
            float p0 = __expf(s0 - mnew);
            float p1 = __expf(s1 - mnew);
            float ps = p0 + p1;
#pragma unroll
            for (int off = 16; off; off >>= 1)
                ps += __shfl_xor_sync(0xffffffffu, ps, off);
            float alpha = __expf(m[r] - mnew);
            lsum[r] = lsum[r] * alpha + ps;
            m[r] = mnew;
            o0[r] *= alpha;
            o1[r] *= alpha;
            Pw[r * PS + l] = p0;
            Pw[r * PS + l + 32] = p1;
        }
        __syncwarp();

        // ---- O += P * V (V = Ks). Lane owns output dims {l, l+32}. ----
#pragma unroll
        for (int cb = 0; cb < 64; cb += 8) {
            float v0[8], v1[8];
#pragma unroll
            for (int cc = 0; cc < 8; cc++) {
                v0[cc] = Ks[(cb + cc) * PS + l];
                v1[cc] = Ks[(cb + cc) * PS + l + 32];
            }
#pragma unroll
            for (int r = 0; r < 4; r++) {
                float4 pa = *(const float4*)(Pw + r * PS + cb);
                float4 pb = *(const float4*)(Pw + r * PS + cb + 4);
                o0[r] += pa.x * v0[0] + pa.y * v0[1] + pa.z * v0[2] + pa.w * v0[3]
                       + pb.x * v0[4] + pb.y * v0[5] + pb.z * v0[6] + pb.w * v0[7];
                o1[r] += pa.x * v1[0] + pa.y * v1[1] + pa.z * v1[2] + pa.w * v1[3]
                       + pb.x * v1[4] + pb.y * v1[5] + pb.z * v1[6] + pb.w * v1[7];
            }
        }
    }

    float* ob = out + (size_t)b * TT * HEAD;
#pragma unroll
    for (int r = 0; r < 4; r++) {
        float inv = 1.0f / lsum[r];
        int t = t0 + rr0 + r;
        ob[t * HEAD + l] = o0[r] * inv;
        ob[t * HEAD + l + 32] = o1[r] * inv;
    }
}

// ---------------------------------------------------------------------------
extern "C" void kernel_launch(void* const* d_in, const int* in_sizes, int n_in,
                              void* d_out, int out_size) {
    const float* x   = (const float*)d_in[0];
    const float* Wq  = (const float*)d_in[1];
    const float* rel = (const float*)d_in[2];
    float* out = (float*)d_out;

    dim3 pgrid(TT / 32, BB);
    proj_kernel<<<pgrid, 128>>>(x, Wq);

    dim3 agrid(TT / 16, BB);
    attn_kernel<<<agrid, 128>>>(rel, out);
}